// round 1
// baseline (speedup 1.0000x reference)
#include <cuda_runtime.h>
#include <math.h>
#include <stdint.h>

// ---------------- problem constants ----------------
#define B   512
#define D   256
#define C   100000

#define S_SCALE   30.0f
#define COS_M     0.8775825618903728f   // cos(0.5)
#define SIN_M     0.479425538604203f    // sin(0.5)
#define THRESH   (-0.8775825618903728f) // cos(pi-0.5)
#define MM_CONST  0.2397127693021015f   // sin(pi-0.5)*0.5
#define EPS_N     1e-12f

#define PRED_ELEMS   ((size_t)B * C)        // 51,200,000
#define W_ELEMS      ((size_t)C * D)        // 25,600,000

// ---------------- device scratch (small) ----------------
__device__ float g_fnorm[B * D];
__device__ float g_tl[B];
__device__ float g_ctm[B];
__device__ float g_ftl[B];
__device__ float g_tnew;
__device__ int   g_counts[C];
__device__ int   g_targets[B];

// ---------------- helpers ----------------
__device__ __forceinline__ float block_reduce_sum(float v) {
    __shared__ float s[32];
    int lane = threadIdx.x & 31;
    int w    = threadIdx.x >> 5;
    #pragma unroll
    for (int o = 16; o; o >>= 1) v += __shfl_down_sync(0xffffffffu, v, o);
    __syncthreads();                 // protect s[] reuse across calls
    if (lane == 0) s[w] = v;
    __syncthreads();
    int nw = blockDim.x >> 5;
    v = (threadIdx.x < nw) ? s[threadIdx.x] : 0.0f;
    if (w == 0) {
        #pragma unroll
        for (int o = 16; o; o >>= 1) v += __shfl_down_sync(0xffffffffu, v, o);
        if (lane == 0) s[0] = v;
    }
    __syncthreads();
    return s[0];
}

// ---------------- kernel 1: unpack targets (int32 vs int64 detection) ----------------
__global__ void k_unpack_targets(const int* __restrict__ traw) {
    __shared__ int oddnz;
    if (threadIdx.x == 0) oddnz = 0;
    __syncthreads();
    if (threadIdx.x < B / 2) {
        // only reads first B ints (safe for both dtypes)
        if (traw[2 * threadIdx.x + 1] != 0) atomicOr(&oddnz, 1);
    }
    __syncthreads();
    int is64 = (oddnz == 0);
    int b = threadIdx.x;
    g_targets[b] = is64 ? traw[2 * b] : traw[b];
}

// ---------------- kernel 2: normalize features + target logit ----------------
__global__ void k_normalize_tl(const float* __restrict__ features,
                               const float* __restrict__ weight) {
    int b = blockIdx.x;
    int d = threadIdx.x;
    float v = features[b * D + d];
    float ss = block_reduce_sum(v * v);
    float inv = 1.0f / fmaxf(sqrtf(ss), EPS_N);
    float f = v * inv;
    g_fnorm[b * D + d] = f;
    int tgt = g_targets[b];
    float p = f * weight[(size_t)tgt * D + d];
    float dot = block_reduce_sum(p);
    if (d == 0) g_tl[b] = dot;
}

// ---------------- kernel 3: t_new + per-row margin params ----------------
__global__ void k_row_params(const float* __restrict__ t_in,
                             float* __restrict__ out_t) {
    int b = threadIdx.x;           // blockDim = 512
    float tl = g_tl[b];
    float m = block_reduce_sum(tl) * (1.0f / (float)B);
    if (b == 0) {
        float tn = m * 0.01f + 0.99f * t_in[0];
        g_tnew = tn;
        out_t[0] = tn;
    }
    float sn = sqrtf(fmaxf(1.0f - tl * tl, 0.0f));
    float ctm = tl * COS_M - sn * SIN_M;
    g_ctm[b] = ctm;
    g_ftl[b] = (tl > THRESH) ? ctm : (tl - MM_CONST);
}

// ---------------- kernel 4: zero counts ----------------
__global__ void k_zero_counts() {
    int i = blockIdx.x * blockDim.x + threadIdx.x;
    if (i < C) g_counts[i] = 0;
}

// ---------------- kernel 5: zero scratch rows for touched classes ----------------
__global__ void k_zero_scratch(float* __restrict__ scratch) {
    int b = blockIdx.x;
    int d = threadIdx.x;
    int tgt = g_targets[b];
    scratch[(size_t)tgt * D + d] = 0.0f;
}

// ---------------- kernel 6: segment-sum accumulate ----------------
__global__ void k_accumulate(float* __restrict__ scratch) {
    int b = blockIdx.x;
    int d = threadIdx.x;
    int tgt = g_targets[b];
    atomicAdd(&scratch[(size_t)tgt * D + d], g_fnorm[b * D + d]);
    if (d == 0) atomicAdd(&g_counts[tgt], 1);
}

// ---------------- kernel 7: memory-bank weight update ----------------
__global__ void k_weight_update(const float* __restrict__ weight,
                                const float* __restrict__ scratch,
                                float* __restrict__ newW) {
    int c = blockIdx.x;
    int d = threadIdx.x;
    size_t idx = (size_t)c * D + d;
    float w = weight[idx];
    int cnt = g_counts[c];
    float out;
    if (cnt > 0) {
        float u = 0.5f * w + 0.5f * (scratch[idx] / (float)cnt);
        float ss = block_reduce_sum(u * u);
        out = u / fmaxf(sqrtf(ss), EPS_N);
    } else {
        out = w;
    }
    newW[idx] = out;
}

// ---------------- kernel 8: GEMM + ArcFace epilogue ----------------
// pred[b][c] = epilogue( sum_d f[b][d] * W[c][d] )
// Tile: BM=128 (b), BN=128 (c), BK=16. 256 threads, 8x8 micro-tile each.
#define BM 128
#define BN 128
#define BK 16
#define PAD 4

__global__ void __launch_bounds__(256, 2)
k_gemm_epilogue(const float* __restrict__ W, float* __restrict__ pred) {
    __shared__ float As[BK][BM + PAD];
    __shared__ float Ws[BK][BN + PAD];

    const int c0 = blockIdx.x * BN;
    const int b0 = blockIdx.y * BM;
    const int tx = threadIdx.x & 15;   // c direction
    const int ty = threadIdx.x >> 4;   // b direction

    float acc[8][8];
    #pragma unroll
    for (int i = 0; i < 8; ++i)
        #pragma unroll
        for (int j = 0; j < 8; ++j) acc[i][j] = 0.0f;

    for (int kt = 0; kt < D; kt += BK) {
        // ---- load tiles: 128 rows x 16 k each, 2 float4 per thread per matrix
        #pragma unroll
        for (int r = 0; r < 2; ++r) {
            int idx = threadIdx.x + r * 256;
            int row = idx >> 2;          // 0..127
            int kc  = (idx & 3) * 4;     // 0,4,8,12
            float4 va = *(const float4*)&g_fnorm[(b0 + row) * D + kt + kc];
            As[kc + 0][row] = va.x; As[kc + 1][row] = va.y;
            As[kc + 2][row] = va.z; As[kc + 3][row] = va.w;
            int cg = c0 + row;
            float4 vw = make_float4(0.f, 0.f, 0.f, 0.f);
            if (cg < C) vw = *(const float4*)&W[(size_t)cg * D + kt + kc];
            Ws[kc + 0][row] = vw.x; Ws[kc + 1][row] = vw.y;
            Ws[kc + 2][row] = vw.z; Ws[kc + 3][row] = vw.w;
        }
        __syncthreads();

        #pragma unroll
        for (int k = 0; k < BK; ++k) {
            float4 a0 = *(const float4*)&As[k][ty * 8];
            float4 a1 = *(const float4*)&As[k][ty * 8 + 4];
            float4 w0 = *(const float4*)&Ws[k][tx * 8];
            float4 w1 = *(const float4*)&Ws[k][tx * 8 + 4];
            float af[8] = {a0.x, a0.y, a0.z, a0.w, a1.x, a1.y, a1.z, a1.w};
            float wf[8] = {w0.x, w0.y, w0.z, w0.w, w1.x, w1.y, w1.z, w1.w};
            #pragma unroll
            for (int i = 0; i < 8; ++i)
                #pragma unroll
                for (int j = 0; j < 8; ++j)
                    acc[i][j] = fmaf(af[i], wf[j], acc[i][j]);
        }
        __syncthreads();
    }

    // ---- ArcFace epilogue + store
    const float tn = g_tnew;
    #pragma unroll
    for (int i = 0; i < 8; ++i) {
        int b = b0 + ty * 8 + i;
        int tgt = g_targets[b];
        float ctm = g_ctm[b];
        float ftl = g_ftl[b];
        float vals[8];
        #pragma unroll
        for (int j = 0; j < 8; ++j) {
            int c = c0 + tx * 8 + j;
            float cs = acc[i][j];
            float v = (cs > ctm) ? cs * (tn + cs) : cs;
            if (c == tgt) v = ftl;
            vals[j] = v * S_SCALE;
        }
        size_t base = (size_t)b * C + c0 + tx * 8;
        #pragma unroll
        for (int q = 0; q < 2; ++q) {
            int cb = c0 + tx * 8 + q * 4;
            if (cb + 3 < C) {
                *(float4*)&pred[base + q * 4] =
                    make_float4(vals[q*4+0], vals[q*4+1], vals[q*4+2], vals[q*4+3]);
            } else {
                #pragma unroll
                for (int j = 0; j < 4; ++j)
                    if (cb + j < C) pred[base + q * 4 + j] = vals[q * 4 + j];
            }
        }
    }
}

// ---------------- launch ----------------
extern "C" void kernel_launch(void* const* d_in, const int* in_sizes, int n_in,
                              void* d_out, int out_size) {
    const float* features = (const float*)d_in[0];
    const int*   traw     = (const int*)d_in[1];
    const float* weight   = (const float*)d_in[2];
    const float* t_in     = (const float*)d_in[3];

    float* out    = (float*)d_out;
    float* pred   = out;                       // [B, C]
    float* newW   = out + PRED_ELEMS;          // [C, D]
    float* out_t  = out + PRED_ELEMS + W_ELEMS;// [1]
    float* scratch = pred;                     // reuse pred region as segment-sum scratch

    k_unpack_targets<<<1, B>>>(traw);
    k_normalize_tl<<<B, D>>>(features, weight);
    k_row_params<<<1, B>>>(t_in, out_t);
    k_zero_counts<<<(C + 255) / 256, 256>>>();
    k_zero_scratch<<<B, D>>>(scratch);
    k_accumulate<<<B, D>>>(scratch);
    k_weight_update<<<C, D>>>(weight, scratch, newW);

    dim3 grid((C + BN - 1) / BN, B / BM);      // 782 x 4
    k_gemm_epilogue<<<grid, 256>>>(weight, pred);
}

// round 3
// speedup vs baseline: 1.6610x; 1.6610x over previous
#include <cuda_runtime.h>
#include <cuda_bf16.h>
#include <math.h>
#include <stdint.h>

// ---------------- problem constants ----------------
#define B   512
#define D   256
#define C   100000
#define CPAD 100096              // padded to multiple of 128
#define KCAT 768                 // 3*D concatenated bf16 K

#define S_SCALE   30.0f
#define COS_M     0.8775825618903728f
#define SIN_M     0.479425538604203f
#define THRESH   (-0.8775825618903728f)
#define MM_CONST  0.2397127693021015f
#define EPS_N     1e-12f

#define PRED_ELEMS   ((size_t)B * C)
#define W_ELEMS      ((size_t)C * D)

// ---------------- device scratch ----------------
__device__ float g_fnorm[B * D];
__device__ float g_tl[B];
__device__ float g_ctm[B];
__device__ float g_ftl[B];
__device__ float g_tnew;
__device__ int   g_counts[C];
__device__ int   g_targets[B];
__device__ __nv_bfloat16 g_A[B * KCAT];                   // [512, 768] = [fhi|flo|fhi]
__device__ __nv_bfloat16 g_Bw[(size_t)CPAD * KCAT];       // [100096, 768] = [Whi|Whi|Wlo]

// ---------------- PTX helpers (baseline sm_80+ only) ----------------
__device__ __forceinline__ uint32_t smem_u32(const void* p) {
    uint32_t a;
    asm("{ .reg .u64 t; cvta.to.shared.u64 t, %1; cvt.u32.u64 %0, t; }" : "=r"(a) : "l"(p));
    return a;
}
__device__ __forceinline__ void cp16(uint32_t dst, const void* src) {
    asm volatile("cp.async.cg.shared.global [%0], [%1], 16;" :: "r"(dst), "l"(src));
}
#define CP_COMMIT()  asm volatile("cp.async.commit_group;" ::: "memory")
#define CP_WAIT1()   asm volatile("cp.async.wait_group 1;" ::: "memory")
#define CP_WAIT0()   asm volatile("cp.async.wait_group 0;" ::: "memory")

__device__ __forceinline__ void mma16816(float* d, const uint32_t* a, const uint32_t* b) {
    asm volatile(
        "mma.sync.aligned.m16n8k16.row.col.f32.bf16.bf16.f32 "
        "{%0,%1,%2,%3}, {%4,%5,%6,%7}, {%8,%9}, {%0,%1,%2,%3};"
        : "+f"(d[0]), "+f"(d[1]), "+f"(d[2]), "+f"(d[3])
        : "r"(a[0]), "r"(a[1]), "r"(a[2]), "r"(a[3]), "r"(b[0]), "r"(b[1]));
}

// ---------------- small helper ----------------
__device__ __forceinline__ float block_reduce_sum(float v) {
    __shared__ float s[32];
    int lane = threadIdx.x & 31;
    int w    = threadIdx.x >> 5;
    #pragma unroll
    for (int o = 16; o; o >>= 1) v += __shfl_down_sync(0xffffffffu, v, o);
    __syncthreads();
    if (lane == 0) s[w] = v;
    __syncthreads();
    int nw = blockDim.x >> 5;
    v = (threadIdx.x < nw) ? s[threadIdx.x] : 0.0f;
    if (w == 0) {
        #pragma unroll
        for (int o = 16; o; o >>= 1) v += __shfl_down_sync(0xffffffffu, v, o);
        if (lane == 0) s[0] = v;
    }
    __syncthreads();
    return s[0];
}

// ---------------- kernel 1: unpack targets (int32 vs int64 detection) ----------------
__global__ void k_unpack_targets(const int* __restrict__ traw) {
    __shared__ int oddnz;
    if (threadIdx.x == 0) oddnz = 0;
    __syncthreads();
    if (threadIdx.x < B / 2) {
        if (traw[2 * threadIdx.x + 1] != 0) atomicOr(&oddnz, 1);
    }
    __syncthreads();
    int is64 = (oddnz == 0);
    int b = threadIdx.x;
    g_targets[b] = is64 ? traw[2 * b] : traw[b];
}

// ---------------- kernel 2: normalize features + target logit + A' split ----------------
__global__ void k_normalize_tl(const float* __restrict__ features,
                               const float* __restrict__ weight) {
    int b = blockIdx.x;
    int d = threadIdx.x;
    float v = features[b * D + d];
    float ss = block_reduce_sum(v * v);
    float inv = 1.0f / fmaxf(sqrtf(ss), EPS_N);
    float f = v * inv;
    g_fnorm[b * D + d] = f;

    __nv_bfloat16 hi = __float2bfloat16(f);
    __nv_bfloat16 lo = __float2bfloat16(f - __bfloat162float(hi));
    g_A[b * KCAT + d]         = hi;
    g_A[b * KCAT + D + d]     = lo;
    g_A[b * KCAT + 2 * D + d] = hi;

    int tgt = g_targets[b];
    float p = f * weight[(size_t)tgt * D + d];
    float dot = block_reduce_sum(p);
    if (d == 0) g_tl[b] = dot;
}

// ---------------- kernel 3: t_new + per-row margin params ----------------
__global__ void k_row_params(const float* __restrict__ t_in,
                             float* __restrict__ out_t) {
    int b = threadIdx.x;           // blockDim = 512
    float tl = g_tl[b];
    float m = block_reduce_sum(tl) * (1.0f / (float)B);
    if (b == 0) {
        float tn = m * 0.01f + 0.99f * t_in[0];
        g_tnew = tn;
        out_t[0] = tn;
    }
    float sn = sqrtf(fmaxf(1.0f - tl * tl, 0.0f));
    float ctm = tl * COS_M - sn * SIN_M;
    g_ctm[b] = ctm;
    g_ftl[b] = (tl > THRESH) ? ctm : (tl - MM_CONST);
}

// ---------------- kernel 4: zero counts ----------------
__global__ void k_zero_counts() {
    int i = blockIdx.x * blockDim.x + threadIdx.x;
    if (i < C) g_counts[i] = 0;
}

// ---------------- kernel 5: zero scratch rows for touched classes ----------------
__global__ void k_zero_scratch(float* __restrict__ scratch) {
    int b = blockIdx.x;
    int d = threadIdx.x;
    int tgt = g_targets[b];
    scratch[(size_t)tgt * D + d] = 0.0f;
}

// ---------------- kernel 6: segment-sum accumulate ----------------
__global__ void k_accumulate(float* __restrict__ scratch) {
    int b = blockIdx.x;
    int d = threadIdx.x;
    int tgt = g_targets[b];
    atomicAdd(&scratch[(size_t)tgt * D + d], g_fnorm[b * D + d]);
    if (d == 0) atomicAdd(&g_counts[tgt], 1);
}

// ---------------- kernel 7: weight update + B' bf16 split conversion ----------------
__global__ void k_weight_update(const float* __restrict__ weight,
                                const float* __restrict__ scratch,
                                float* __restrict__ newW) {
    int c = blockIdx.x;            // grid = CPAD
    int d = threadIdx.x;
    if (c >= C) {
        size_t kb = (size_t)c * KCAT;
        __nv_bfloat16 z = __float2bfloat16(0.0f);
        g_Bw[kb + d] = z; g_Bw[kb + D + d] = z; g_Bw[kb + 2 * D + d] = z;
        return;
    }
    size_t idx = (size_t)c * D + d;
    float w = weight[idx];

    __nv_bfloat16 hi = __float2bfloat16(w);
    __nv_bfloat16 lo = __float2bfloat16(w - __bfloat162float(hi));
    size_t kb = (size_t)c * KCAT;
    g_Bw[kb + d]         = hi;
    g_Bw[kb + D + d]     = hi;
    g_Bw[kb + 2 * D + d] = lo;

    int cnt = g_counts[c];
    float out;
    if (cnt > 0) {
        float u = 0.5f * w + 0.5f * (scratch[idx] / (float)cnt);
        float ss = block_reduce_sum(u * u);
        out = u / fmaxf(sqrtf(ss), EPS_N);
    } else {
        out = w;
    }
    newW[idx] = out;
}

// ---------------- kernel 8: mma.sync GEMM + ArcFace epilogue ----------------
// CTA: 128(m) x 128(n), BK=64 bf16, 2-stage cp.async pipeline.
// 8 warps in 2(m) x 4(n); warp tile 64 x 32; mma.sync.m16n8k16 bf16.
#define BKB      64
#define NCH      (KCAT / BKB)           // 12
#define STRIDE   144                    // padded row bytes (64*2 + 16)
#define TILE_B   (128 * STRIDE)         // 18432
#define STAGE_B  (2 * TILE_B)           // 36864 (A tile + B tile)
#define SMEM_G   (2 * STAGE_B)          // 73728

__device__ __forceinline__ void load_tiles(int chunk, int stage, uint32_t sb,
                                           int m0, int n0) {
    uint32_t abase = sb + stage * STAGE_B;
    uint32_t bbase = abase + TILE_B;
    const char* Asrc = (const char*)g_A;
    const char* Bsrc = (const char*)g_Bw;
    #pragma unroll
    for (int i = 0; i < 4; ++i) {
        int idx = threadIdx.x + i * 256;
        int row = idx >> 3, seg = idx & 7;
        uint32_t so = row * STRIDE + seg * 16;
        size_t goff = ((size_t)row * KCAT + chunk * BKB) * 2 + seg * 16;
        cp16(abase + so, Asrc + (size_t)m0 * KCAT * 2 + goff);
        cp16(bbase + so, Bsrc + (size_t)n0 * KCAT * 2 + goff);
    }
    CP_COMMIT();
}

__global__ void __launch_bounds__(256, 1)
k_gemm_mma(float* __restrict__ pred) {
    extern __shared__ char smem[];
    uint32_t sb = smem_u32(smem);
    const int tid  = threadIdx.x;
    const int wid  = tid >> 5;
    const int lane = tid & 31;
    const int wm   = wid >> 2;          // 0..1
    const int wn   = wid & 3;           // 0..3
    const int g    = lane >> 2;         // 0..7
    const int tig  = lane & 3;          // 0..3
    const int m0   = blockIdx.x * 128;  // m fastest -> B-tile L2 reuse
    const int n0   = blockIdx.y * 128;

    float acc[4][4][4];
    #pragma unroll
    for (int i = 0; i < 4; ++i)
        #pragma unroll
        for (int j = 0; j < 4; ++j)
            #pragma unroll
            for (int r = 0; r < 4; ++r) acc[i][j][r] = 0.0f;

    load_tiles(0, 0, sb, m0, n0);
    load_tiles(1, 1, sb, m0, n0);

    for (int j = 0; j < NCH; ++j) {
        if (j + 1 < NCH) { CP_WAIT1(); } else { CP_WAIT0(); }
        __syncthreads();
        const int stage = j & 1;
        const char* At = smem + stage * STAGE_B;
        const char* Bt = At + TILE_B;

        #pragma unroll
        for (int kk = 0; kk < 4; ++kk) {
            uint32_t a[4][4], b[4][2];
            #pragma unroll
            for (int mi = 0; mi < 4; ++mi) {
                const char* p = At + (wm * 64 + mi * 16 + g) * STRIDE + kk * 32 + tig * 4;
                a[mi][0] = *(const uint32_t*)p;
                a[mi][1] = *(const uint32_t*)(p + 8 * STRIDE);
                a[mi][2] = *(const uint32_t*)(p + 16);
                a[mi][3] = *(const uint32_t*)(p + 8 * STRIDE + 16);
            }
            #pragma unroll
            for (int nj = 0; nj < 4; ++nj) {
                const char* p = Bt + (wn * 32 + nj * 8 + g) * STRIDE + kk * 32 + tig * 4;
                b[nj][0] = *(const uint32_t*)p;
                b[nj][1] = *(const uint32_t*)(p + 16);
            }
            #pragma unroll
            for (int mi = 0; mi < 4; ++mi)
                #pragma unroll
                for (int nj = 0; nj < 4; ++nj)
                    mma16816(acc[mi][nj], a[mi], b[nj]);
        }
        __syncthreads();                        // stage free before refill
        if (j + 2 < NCH) load_tiles(j + 2, stage, sb, m0, n0);
    }

    // ---- fused ArcFace epilogue ----
    const float tn = g_tnew;
    #pragma unroll
    for (int mi = 0; mi < 4; ++mi) {
        int r0 = m0 + wm * 64 + mi * 16 + g;
        #pragma unroll
        for (int half = 0; half < 2; ++half) {
            int brow = r0 + half * 8;
            int tgt   = g_targets[brow];
            float ctm = g_ctm[brow];
            float ftl = g_ftl[brow];
            size_t rowbase = (size_t)brow * C;
            #pragma unroll
            for (int nj = 0; nj < 4; ++nj) {
                int c = n0 + wn * 32 + nj * 8 + tig * 2;
                float v0 = acc[mi][nj][half * 2 + 0];
                float v1 = acc[mi][nj][half * 2 + 1];
                v0 = (v0 > ctm) ? v0 * (tn + v0) : v0;
                v1 = (v1 > ctm) ? v1 * (tn + v1) : v1;
                if (c == tgt)     v0 = ftl;
                if (c + 1 == tgt) v1 = ftl;
                v0 *= S_SCALE;
                v1 *= S_SCALE;
                if (c + 1 < C) {
                    *(float2*)&pred[rowbase + c] = make_float2(v0, v1);
                } else if (c < C) {
                    pred[rowbase + c] = v0;
                }
            }
        }
    }
}

// ---------------- launch ----------------
extern "C" void kernel_launch(void* const* d_in, const int* in_sizes, int n_in,
                              void* d_out, int out_size) {
    const float* features = (const float*)d_in[0];
    const int*   traw     = (const int*)d_in[1];
    const float* weight   = (const float*)d_in[2];
    const float* t_in     = (const float*)d_in[3];

    float* out    = (float*)d_out;
    float* pred   = out;                        // [B, C]
    float* newW   = out + PRED_ELEMS;           // [C, D]
    float* out_t  = out + PRED_ELEMS + W_ELEMS; // [1]
    float* scratch = pred;                      // reuse pred region as segment-sum scratch

    cudaFuncSetAttribute(k_gemm_mma, cudaFuncAttributeMaxDynamicSharedMemorySize, SMEM_G);

    k_unpack_targets<<<1, B>>>(traw);
    k_normalize_tl<<<B, D>>>(features, weight);
    k_row_params<<<1, B>>>(t_in, out_t);
    k_zero_counts<<<(C + 255) / 256, 256>>>();
    k_zero_scratch<<<B, D>>>(scratch);
    k_accumulate<<<B, D>>>(scratch);
    k_weight_update<<<CPAD, D>>>(weight, scratch, newW);

    dim3 grid(B / 128, CPAD / 128);             // (4, 782), m fastest
    k_gemm_mma<<<grid, 256, SMEM_G>>>(pred);
}

// round 4
// speedup vs baseline: 2.1086x; 1.2695x over previous
#include <cuda_runtime.h>
#include <cuda_bf16.h>
#include <math.h>
#include <stdint.h>

// ---------------- problem constants ----------------
#define B   512
#define D   256
#define C   100000
#define CPAD 100096              // padded to multiple of 128
#define KCAT 768                 // 3*D concatenated bf16 K

#define S_SCALE   30.0f
#define COS_M     0.8775825618903728f
#define SIN_M     0.479425538604203f
#define THRESH   (-0.8775825618903728f)
#define MM_CONST  0.2397127693021015f
#define EPS_N     1e-12f

#define PRED_ELEMS   ((size_t)B * C)
#define W_ELEMS      ((size_t)C * D)

// ---------------- device scratch ----------------
__device__ float g_fnorm[B * D];
__device__ float g_tl[B];
__device__ float g_ctm[B];
__device__ float g_ftl[B];
__device__ float g_tnew;
__device__ int   g_counts[C];
__device__ int   g_targets[B];
__device__ __nv_bfloat16 g_A[B * KCAT];                   // [512, 768] = [fhi|flo|fhi]
__device__ __nv_bfloat16 g_Bw[(size_t)CPAD * KCAT];       // [100096, 768] = [Whi|Whi|Wlo]

// ---------------- PTX helpers (baseline sm_80+ only) ----------------
__device__ __forceinline__ uint32_t smem_u32(const void* p) {
    uint32_t a;
    asm("{ .reg .u64 t; cvta.to.shared.u64 t, %1; cvt.u32.u64 %0, t; }" : "=r"(a) : "l"(p));
    return a;
}
__device__ __forceinline__ void cp16(uint32_t dst, const void* src) {
    asm volatile("cp.async.cg.shared.global [%0], [%1], 16;" :: "r"(dst), "l"(src));
}
#define CP_COMMIT()  asm volatile("cp.async.commit_group;" ::: "memory")
#define CP_WAIT1()   asm volatile("cp.async.wait_group 1;" ::: "memory")
#define CP_WAIT0()   asm volatile("cp.async.wait_group 0;" ::: "memory")

__device__ __forceinline__ void ldsm4(uint32_t* r, uint32_t addr) {
    asm volatile("ldmatrix.sync.aligned.m8n8.x4.shared.b16 {%0,%1,%2,%3}, [%4];"
                 : "=r"(r[0]), "=r"(r[1]), "=r"(r[2]), "=r"(r[3]) : "r"(addr));
}
__device__ __forceinline__ void mma16816(float* d, const uint32_t* a, const uint32_t* b) {
    asm volatile(
        "mma.sync.aligned.m16n8k16.row.col.f32.bf16.bf16.f32 "
        "{%0,%1,%2,%3}, {%4,%5,%6,%7}, {%8,%9}, {%0,%1,%2,%3};"
        : "+f"(d[0]), "+f"(d[1]), "+f"(d[2]), "+f"(d[3])
        : "r"(a[0]), "r"(a[1]), "r"(a[2]), "r"(a[3]), "r"(b[0]), "r"(b[1]));
}

// ---------------- small helper ----------------
__device__ __forceinline__ float block_reduce_sum(float v) {
    __shared__ float s[32];
    int lane = threadIdx.x & 31;
    int w    = threadIdx.x >> 5;
    #pragma unroll
    for (int o = 16; o; o >>= 1) v += __shfl_down_sync(0xffffffffu, v, o);
    __syncthreads();
    if (lane == 0) s[w] = v;
    __syncthreads();
    int nw = blockDim.x >> 5;
    v = (threadIdx.x < nw) ? s[threadIdx.x] : 0.0f;
    if (w == 0) {
        #pragma unroll
        for (int o = 16; o; o >>= 1) v += __shfl_down_sync(0xffffffffu, v, o);
        if (lane == 0) s[0] = v;
    }
    __syncthreads();
    return s[0];
}

// ---------------- kernel 1: unpack targets (int32 vs int64 detection) ----------------
__global__ void k_unpack_targets(const int* __restrict__ traw) {
    __shared__ int oddnz;
    if (threadIdx.x == 0) oddnz = 0;
    __syncthreads();
    if (threadIdx.x < B / 2) {
        if (traw[2 * threadIdx.x + 1] != 0) atomicOr(&oddnz, 1);
    }
    __syncthreads();
    int is64 = (oddnz == 0);
    int b = threadIdx.x;
    g_targets[b] = is64 ? traw[2 * b] : traw[b];
}

// ---------------- kernel 2: normalize features + target logit + A' split ----------------
__global__ void k_normalize_tl(const float* __restrict__ features,
                               const float* __restrict__ weight) {
    int b = blockIdx.x;
    int d = threadIdx.x;
    float v = features[b * D + d];
    float ss = block_reduce_sum(v * v);
    float inv = 1.0f / fmaxf(sqrtf(ss), EPS_N);
    float f = v * inv;
    g_fnorm[b * D + d] = f;

    __nv_bfloat16 hi = __float2bfloat16(f);
    __nv_bfloat16 lo = __float2bfloat16(f - __bfloat162float(hi));
    g_A[b * KCAT + d]         = hi;
    g_A[b * KCAT + D + d]     = lo;
    g_A[b * KCAT + 2 * D + d] = hi;

    int tgt = g_targets[b];
    float p = f * weight[(size_t)tgt * D + d];
    float dot = block_reduce_sum(p);
    if (d == 0) g_tl[b] = dot;
}

// ---------------- kernel 3: t_new + per-row margin params ----------------
__global__ void k_row_params(const float* __restrict__ t_in,
                             float* __restrict__ out_t) {
    int b = threadIdx.x;           // blockDim = 512
    float tl = g_tl[b];
    float m = block_reduce_sum(tl) * (1.0f / (float)B);
    if (b == 0) {
        float tn = m * 0.01f + 0.99f * t_in[0];
        g_tnew = tn;
        out_t[0] = tn;
    }
    float sn = sqrtf(fmaxf(1.0f - tl * tl, 0.0f));
    float ctm = tl * COS_M - sn * SIN_M;
    g_ctm[b] = ctm;
    g_ftl[b] = (tl > THRESH) ? ctm : (tl - MM_CONST);
}

// ---------------- kernel 4: zero counts ----------------
__global__ void k_zero_counts() {
    int i = blockIdx.x * blockDim.x + threadIdx.x;
    if (i < C) g_counts[i] = 0;
}

// ---------------- kernel 5: zero scratch rows for touched classes ----------------
__global__ void k_zero_scratch(float* __restrict__ scratch) {
    int b = blockIdx.x;
    int d = threadIdx.x;
    int tgt = g_targets[b];
    scratch[(size_t)tgt * D + d] = 0.0f;
}

// ---------------- kernel 6: segment-sum accumulate ----------------
__global__ void k_accumulate(float* __restrict__ scratch) {
    int b = blockIdx.x;
    int d = threadIdx.x;
    int tgt = g_targets[b];
    atomicAdd(&scratch[(size_t)tgt * D + d], g_fnorm[b * D + d]);
    if (d == 0) atomicAdd(&g_counts[tgt], 1);
}

// ---------------- kernel 7: weight update + B' split (warp per class) ----------------
// 256 threads = 8 warps = 8 classes per block. Each lane handles 8 elements.
__global__ void __launch_bounds__(256)
k_weight_update(const float* __restrict__ weight,
                const float* __restrict__ scratch,
                float* __restrict__ newW) {
    int w    = threadIdx.x >> 5;
    int lane = threadIdx.x & 31;
    int c    = blockIdx.x * 8 + w;
    size_t kb = (size_t)c * KCAT;

    if (c >= C) {
        uint4 z = make_uint4(0, 0, 0, 0);
        *(uint4*)&g_Bw[kb + lane * 8]           = z;
        *(uint4*)&g_Bw[kb + D + lane * 8]       = z;
        *(uint4*)&g_Bw[kb + 2 * D + lane * 8]   = z;
        return;
    }

    size_t idx = (size_t)c * D + lane * 8;
    float4 w0 = *(const float4*)&weight[idx];
    float4 w1 = *(const float4*)&weight[idx + 4];
    float wv[8] = {w0.x, w0.y, w0.z, w0.w, w1.x, w1.y, w1.z, w1.w};

    // bf16 split of OLD weight
    uint32_t hip[4], lop[4];
    #pragma unroll
    for (int i = 0; i < 4; ++i) {
        __nv_bfloat16 h0 = __float2bfloat16(wv[2 * i]);
        __nv_bfloat16 h1 = __float2bfloat16(wv[2 * i + 1]);
        __nv_bfloat16 l0 = __float2bfloat16(wv[2 * i]     - __bfloat162float(h0));
        __nv_bfloat16 l1 = __float2bfloat16(wv[2 * i + 1] - __bfloat162float(h1));
        __nv_bfloat162 hp = __nv_bfloat162(h0, h1);
        __nv_bfloat162 lp = __nv_bfloat162(l0, l1);
        hip[i] = *(uint32_t*)&hp;
        lop[i] = *(uint32_t*)&lp;
    }
    *(uint4*)&g_Bw[kb + lane * 8]         = make_uint4(hip[0], hip[1], hip[2], hip[3]);
    *(uint4*)&g_Bw[kb + D + lane * 8]     = make_uint4(hip[0], hip[1], hip[2], hip[3]);
    *(uint4*)&g_Bw[kb + 2 * D + lane * 8] = make_uint4(lop[0], lop[1], lop[2], lop[3]);

    int cnt = g_counts[c];
    if (cnt > 0) {
        float4 s0 = *(const float4*)&scratch[idx];
        float4 s1 = *(const float4*)&scratch[idx + 4];
        float sv[8] = {s0.x, s0.y, s0.z, s0.w, s1.x, s1.y, s1.z, s1.w};
        float inv_cnt = 1.0f / (float)cnt;
        float u[8], ss = 0.0f;
        #pragma unroll
        for (int i = 0; i < 8; ++i) {
            u[i] = 0.5f * wv[i] + 0.5f * (sv[i] * inv_cnt);
            ss += u[i] * u[i];
        }
        #pragma unroll
        for (int o = 16; o; o >>= 1) ss += __shfl_xor_sync(0xffffffffu, ss, o);
        float inv = 1.0f / fmaxf(sqrtf(ss), EPS_N);
        float4 o0 = make_float4(u[0] * inv, u[1] * inv, u[2] * inv, u[3] * inv);
        float4 o1 = make_float4(u[4] * inv, u[5] * inv, u[6] * inv, u[7] * inv);
        *(float4*)&newW[idx]     = o0;
        *(float4*)&newW[idx + 4] = o1;
    } else {
        *(float4*)&newW[idx]     = w0;
        *(float4*)&newW[idx + 4] = w1;
    }
}

// ---------------- kernel 8: mma.sync GEMM + ArcFace epilogue ----------------
// CTA: 128(m) x 128(n), BK=64 bf16, 2-stage cp.async pipeline.
// 4 warps in 2(m) x 2(n); warp tile 64 x 64; ldmatrix.x4 + mma.sync.m16n8k16.
#define BKB      64
#define NCH      (KCAT / BKB)           // 12
#define STRIDE   144                    // padded row bytes (64*2 + 16)
#define TILE_B   (128 * STRIDE)         // 18432
#define STAGE_B  (2 * TILE_B)           // 36864 (A tile + B tile)
#define SMEM_G   (2 * STAGE_B)          // 73728

__device__ __forceinline__ void load_tiles(int chunk, int stage, uint32_t sb,
                                           int m0, int n0) {
    uint32_t abase = sb + stage * STAGE_B;
    uint32_t bbase = abase + TILE_B;
    const char* Asrc = (const char*)g_A;
    const char* Bsrc = (const char*)g_Bw;
    #pragma unroll
    for (int i = 0; i < 8; ++i) {
        int idx = threadIdx.x + i * 128;
        int row = idx >> 3, seg = idx & 7;
        uint32_t so = row * STRIDE + seg * 16;
        size_t goff = ((size_t)row * KCAT + chunk * BKB) * 2 + seg * 16;
        cp16(abase + so, Asrc + (size_t)m0 * KCAT * 2 + goff);
        cp16(bbase + so, Bsrc + (size_t)n0 * KCAT * 2 + goff);
    }
    CP_COMMIT();
}

__global__ void __launch_bounds__(128, 1)
k_gemm_mma(float* __restrict__ pred) {
    extern __shared__ char smem[];
    uint32_t sb = smem_u32(smem);
    const int tid  = threadIdx.x;
    const int wid  = tid >> 5;
    const int lane = tid & 31;
    const int wm   = wid >> 1;          // 0..1
    const int wn   = wid & 1;           // 0..1
    const int g    = lane >> 2;         // 0..7
    const int tig  = lane & 3;          // 0..3
    const int m0   = blockIdx.x * 128;  // m fastest -> B-tile L2 reuse
    const int n0   = blockIdx.y * 128;

    // per-lane ldmatrix base offsets (within a tile)
    // A: groups (m0-7,k0),(m8-15,k0),(m0-7,k8),(m8-15,k8)
    const uint32_t a_off = (uint32_t)(wm * 64 + (lane & 7) + ((lane >> 3) & 1) * 8) * STRIDE
                         + ((lane >> 4) & 1) * 16;
    // B: groups (n0-7,k0),(n0-7,k8),(n8-15,k0),(n8-15,k8)
    const uint32_t b_off = (uint32_t)(wn * 64 + (lane & 7) + ((lane >> 4) & 1) * 8) * STRIDE
                         + ((lane >> 3) & 1) * 16;

    float acc[4][8][4];
    #pragma unroll
    for (int i = 0; i < 4; ++i)
        #pragma unroll
        for (int j = 0; j < 8; ++j)
            #pragma unroll
            for (int r = 0; r < 4; ++r) acc[i][j][r] = 0.0f;

    load_tiles(0, 0, sb, m0, n0);
    load_tiles(1, 1, sb, m0, n0);

    for (int j = 0; j < NCH; ++j) {
        if (j + 1 < NCH) { CP_WAIT1(); } else { CP_WAIT0(); }
        __syncthreads();
        const int stage = j & 1;
        const uint32_t at = sb + stage * STAGE_B + a_off;
        const uint32_t bt = sb + stage * STAGE_B + TILE_B + b_off;

        #pragma unroll
        for (int kk = 0; kk < 4; ++kk) {
            uint32_t a[4][4], b[8][2];
            #pragma unroll
            for (int mi = 0; mi < 4; ++mi)
                ldsm4(a[mi], at + mi * 16 * STRIDE + kk * 32);
            #pragma unroll
            for (int p = 0; p < 4; ++p) {
                uint32_t r[4];
                ldsm4(r, bt + p * 16 * STRIDE + kk * 32);
                b[2 * p][0]     = r[0];
                b[2 * p][1]     = r[1];
                b[2 * p + 1][0] = r[2];
                b[2 * p + 1][1] = r[3];
            }
            #pragma unroll
            for (int mi = 0; mi < 4; ++mi)
                #pragma unroll
                for (int nj = 0; nj < 8; ++nj)
                    mma16816(acc[mi][nj], a[mi], b[nj]);
        }
        __syncthreads();                        // stage free before refill
        if (j + 2 < NCH) load_tiles(j + 2, stage, sb, m0, n0);
    }

    // ---- fused ArcFace epilogue ----
    const float tn = g_tnew;
    #pragma unroll
    for (int mi = 0; mi < 4; ++mi) {
        int r0 = m0 + wm * 64 + mi * 16 + g;
        #pragma unroll
        for (int half = 0; half < 2; ++half) {
            int brow = r0 + half * 8;
            int tgt   = g_targets[brow];
            float ctm = g_ctm[brow];
            float ftl = g_ftl[brow];
            size_t rowbase = (size_t)brow * C;
            #pragma unroll
            for (int nj = 0; nj < 8; ++nj) {
                int c = n0 + wn * 64 + nj * 8 + tig * 2;
                float v0 = acc[mi][nj][half * 2 + 0];
                float v1 = acc[mi][nj][half * 2 + 1];
                v0 = (v0 > ctm) ? v0 * (tn + v0) : v0;
                v1 = (v1 > ctm) ? v1 * (tn + v1) : v1;
                if (c == tgt)     v0 = ftl;
                if (c + 1 == tgt) v1 = ftl;
                v0 *= S_SCALE;
                v1 *= S_SCALE;
                if (c + 1 < C) {
                    *(float2*)&pred[rowbase + c] = make_float2(v0, v1);
                } else if (c < C) {
                    pred[rowbase + c] = v0;
                }
            }
        }
    }
}

// ---------------- launch ----------------
extern "C" void kernel_launch(void* const* d_in, const int* in_sizes, int n_in,
                              void* d_out, int out_size) {
    const float* features = (const float*)d_in[0];
    const int*   traw     = (const int*)d_in[1];
    const float* weight   = (const float*)d_in[2];
    const float* t_in     = (const float*)d_in[3];

    float* out    = (float*)d_out;
    float* pred   = out;                        // [B, C]
    float* newW   = out + PRED_ELEMS;           // [C, D]
    float* out_t  = out + PRED_ELEMS + W_ELEMS; // [1]
    float* scratch = pred;                      // reuse pred region as segment-sum scratch

    cudaFuncSetAttribute(k_gemm_mma, cudaFuncAttributeMaxDynamicSharedMemorySize, SMEM_G);

    k_unpack_targets<<<1, B>>>(traw);
    k_normalize_tl<<<B, D>>>(features, weight);
    k_row_params<<<1, B>>>(t_in, out_t);
    k_zero_counts<<<(C + 255) / 256, 256>>>();
    k_zero_scratch<<<B, D>>>(scratch);
    k_accumulate<<<B, D>>>(scratch);
    k_weight_update<<<CPAD / 8, 256>>>(weight, scratch, newW);

    dim3 grid(B / 128, CPAD / 128);             // (4, 782), m fastest
    k_gemm_mma<<<grid, 128, SMEM_G>>>(pred);
}

// round 5
// speedup vs baseline: 3.0908x; 1.4658x over previous
#include <cuda_runtime.h>
#include <cuda_bf16.h>
#include <cuda_fp16.h>
#include <math.h>
#include <stdint.h>

// ---------------- problem constants ----------------
#define B   512
#define D   256
#define C   100000
#define CPAD 100096              // padded to multiple of 128
#define KA   512                 // A K-extent: [fhi | flo] fp16
#define KB   256                 // B K-extent: fp16(W)

#define S_SCALE   30.0f
#define COS_M     0.8775825618903728f
#define SIN_M     0.479425538604203f
#define THRESH   (-0.8775825618903728f)
#define MM_CONST  0.2397127693021015f
#define EPS_N     1e-12f

#define PRED_ELEMS   ((size_t)B * C)
#define W_ELEMS      ((size_t)C * D)

// ---------------- device scratch ----------------
__device__ float g_fnorm[B * D];
__device__ float g_tl[B];
__device__ float g_ctm[B];
__device__ float g_ftl[B];
__device__ float g_tnew;
__device__ int   g_counts[C];
__device__ int   g_targets[B];
__device__ __half g_A[B * KA];                    // [512, 512] = [fhi | flo]
__device__ __half g_Bw[(size_t)CPAD * KB];        // [100096, 256] = fp16(W)

// ---------------- PTX helpers (baseline sm_80+ only) ----------------
__device__ __forceinline__ uint32_t smem_u32(const void* p) {
    uint32_t a;
    asm("{ .reg .u64 t; cvta.to.shared.u64 t, %1; cvt.u32.u64 %0, t; }" : "=r"(a) : "l"(p));
    return a;
}
__device__ __forceinline__ void cp16(uint32_t dst, const void* src) {
    asm volatile("cp.async.cg.shared.global [%0], [%1], 16;" :: "r"(dst), "l"(src));
}
#define CP_COMMIT()  asm volatile("cp.async.commit_group;" ::: "memory")
#define CP_WAIT1()   asm volatile("cp.async.wait_group 1;" ::: "memory")
#define CP_WAIT0()   asm volatile("cp.async.wait_group 0;" ::: "memory")

__device__ __forceinline__ void ldsm4(uint32_t* r, uint32_t addr) {
    asm volatile("ldmatrix.sync.aligned.m8n8.x4.shared.b16 {%0,%1,%2,%3}, [%4];"
                 : "=r"(r[0]), "=r"(r[1]), "=r"(r[2]), "=r"(r[3]) : "r"(addr));
}
__device__ __forceinline__ void mma16816(float* d, const uint32_t* a, const uint32_t* b) {
    asm volatile(
        "mma.sync.aligned.m16n8k16.row.col.f32.f16.f16.f32 "
        "{%0,%1,%2,%3}, {%4,%5,%6,%7}, {%8,%9}, {%0,%1,%2,%3};"
        : "+f"(d[0]), "+f"(d[1]), "+f"(d[2]), "+f"(d[3])
        : "r"(a[0]), "r"(a[1]), "r"(a[2]), "r"(a[3]), "r"(b[0]), "r"(b[1]));
}

// ---------------- small helper ----------------
__device__ __forceinline__ float block_reduce_sum(float v) {
    __shared__ float s[32];
    int lane = threadIdx.x & 31;
    int w    = threadIdx.x >> 5;
    #pragma unroll
    for (int o = 16; o; o >>= 1) v += __shfl_down_sync(0xffffffffu, v, o);
    __syncthreads();
    if (lane == 0) s[w] = v;
    __syncthreads();
    int nw = blockDim.x >> 5;
    v = (threadIdx.x < nw) ? s[threadIdx.x] : 0.0f;
    if (w == 0) {
        #pragma unroll
        for (int o = 16; o; o >>= 1) v += __shfl_down_sync(0xffffffffu, v, o);
        if (lane == 0) s[0] = v;
    }
    __syncthreads();
    return s[0];
}

// ---------------- kernel 1: unpack targets (int32 vs int64 detection) ----------------
__global__ void k_unpack_targets(const int* __restrict__ traw) {
    __shared__ int oddnz;
    if (threadIdx.x == 0) oddnz = 0;
    __syncthreads();
    if (threadIdx.x < B / 2) {
        if (traw[2 * threadIdx.x + 1] != 0) atomicOr(&oddnz, 1);
    }
    __syncthreads();
    int is64 = (oddnz == 0);
    int b = threadIdx.x;
    g_targets[b] = is64 ? traw[2 * b] : traw[b];
}

// ---------------- kernel 2: normalize features + target logit + A' split ----------------
__global__ void k_normalize_tl(const float* __restrict__ features,
                               const float* __restrict__ weight) {
    int b = blockIdx.x;
    int d = threadIdx.x;
    float v = features[b * D + d];
    float ss = block_reduce_sum(v * v);
    float inv = 1.0f / fmaxf(sqrtf(ss), EPS_N);
    float f = v * inv;
    g_fnorm[b * D + d] = f;

    __half hi = __float2half(f);
    __half lo = __float2half(f - __half2float(hi));
    g_A[b * KA + d]     = hi;
    g_A[b * KA + D + d] = lo;

    int tgt = g_targets[b];
    float p = f * weight[(size_t)tgt * D + d];
    float dot = block_reduce_sum(p);
    if (d == 0) g_tl[b] = dot;
}

// ---------------- kernel 3: t_new + per-row margin params ----------------
__global__ void k_row_params(const float* __restrict__ t_in,
                             float* __restrict__ out_t) {
    int b = threadIdx.x;           // blockDim = 512
    float tl = g_tl[b];
    float m = block_reduce_sum(tl) * (1.0f / (float)B);
    if (b == 0) {
        float tn = m * 0.01f + 0.99f * t_in[0];
        g_tnew = tn;
        out_t[0] = tn;
    }
    float sn = sqrtf(fmaxf(1.0f - tl * tl, 0.0f));
    float ctm = tl * COS_M - sn * SIN_M;
    g_ctm[b] = ctm;
    g_ftl[b] = (tl > THRESH) ? ctm : (tl - MM_CONST);
}

// ---------------- kernel 4: zero counts ----------------
__global__ void k_zero_counts() {
    int i = blockIdx.x * blockDim.x + threadIdx.x;
    if (i < C) g_counts[i] = 0;
}

// ---------------- kernel 5: zero scratch rows for touched classes ----------------
__global__ void k_zero_scratch(float* __restrict__ scratch) {
    int b = blockIdx.x;
    int d = threadIdx.x;
    int tgt = g_targets[b];
    scratch[(size_t)tgt * D + d] = 0.0f;
}

// ---------------- kernel 6: segment-sum accumulate ----------------
__global__ void k_accumulate(float* __restrict__ scratch) {
    int b = blockIdx.x;
    int d = threadIdx.x;
    int tgt = g_targets[b];
    atomicAdd(&scratch[(size_t)tgt * D + d], g_fnorm[b * D + d]);
    if (d == 0) atomicAdd(&g_counts[tgt], 1);
}

// ---------------- kernel 7: weight update + fp16(W) conversion (warp/class) ---------
// 256 threads = 8 warps = 8 classes per block. Each lane handles 8 elements.
__global__ void __launch_bounds__(256)
k_weight_update(const float* __restrict__ weight,
                const float* __restrict__ scratch,
                float* __restrict__ newW) {
    int w    = threadIdx.x >> 5;
    int lane = threadIdx.x & 31;
    int c    = blockIdx.x * 8 + w;
    size_t kb = (size_t)c * KB;

    if (c >= C) {
        *(uint4*)&g_Bw[kb + lane * 8] = make_uint4(0, 0, 0, 0);
        return;
    }

    size_t idx = (size_t)c * D + lane * 8;
    float4 w0 = *(const float4*)&weight[idx];
    float4 w1 = *(const float4*)&weight[idx + 4];
    float wv[8] = {w0.x, w0.y, w0.z, w0.w, w1.x, w1.y, w1.z, w1.w};

    // fp16 conversion of OLD weight for the logits GEMM
    uint32_t hp[4];
    #pragma unroll
    for (int i = 0; i < 4; ++i) {
        __half2 h = __floats2half2_rn(wv[2 * i], wv[2 * i + 1]);
        hp[i] = *(uint32_t*)&h;
    }
    *(uint4*)&g_Bw[kb + lane * 8] = make_uint4(hp[0], hp[1], hp[2], hp[3]);

    int cnt = g_counts[c];
    if (cnt > 0) {
        float4 s0 = *(const float4*)&scratch[idx];
        float4 s1 = *(const float4*)&scratch[idx + 4];
        float sv[8] = {s0.x, s0.y, s0.z, s0.w, s1.x, s1.y, s1.z, s1.w};
        float inv_cnt = 1.0f / (float)cnt;
        float u[8], ss = 0.0f;
        #pragma unroll
        for (int i = 0; i < 8; ++i) {
            u[i] = 0.5f * wv[i] + 0.5f * (sv[i] * inv_cnt);
            ss += u[i] * u[i];
        }
        #pragma unroll
        for (int o = 16; o; o >>= 1) ss += __shfl_xor_sync(0xffffffffu, ss, o);
        float inv = 1.0f / fmaxf(sqrtf(ss), EPS_N);
        float4 o0 = make_float4(u[0] * inv, u[1] * inv, u[2] * inv, u[3] * inv);
        float4 o1 = make_float4(u[4] * inv, u[5] * inv, u[6] * inv, u[7] * inv);
        *(float4*)&newW[idx]     = o0;
        *(float4*)&newW[idx + 4] = o1;
    } else {
        *(float4*)&newW[idx]     = w0;
        *(float4*)&newW[idx + 4] = w1;
    }
}

// ---------------- kernel 8: mma.sync GEMM + ArcFace epilogue ----------------
// CTA: 128(m) x 128(n), BK=64 fp16, 2-stage cp.async pipeline.
// K' = 512 (A = [fhi|flo]); B chunk index = (j & 3) — B re-read hits L2.
// 4 warps in 2(m) x 2(n); warp tile 64 x 64; ldmatrix.x4 + mma.sync.m16n8k16.
#define BKE      64                     // K elements per chunk
#define NCH      (KA / BKE)             // 8
#define STRIDE   144                    // padded row bytes (64*2 + 16)
#define TILE_B   (128 * STRIDE)         // 18432
#define STAGE_B  (2 * TILE_B)           // 36864 (A tile + B tile)
#define SMEM_G   (2 * STAGE_B)          // 73728

__device__ __forceinline__ void load_tiles(int chunk, int stage, uint32_t sb,
                                           int m0, int n0) {
    uint32_t abase = sb + stage * STAGE_B;
    uint32_t bbase = abase + TILE_B;
    const char* Asrc = (const char*)g_A;
    const char* Bsrc = (const char*)g_Bw;
    const int bchunk = chunk & 3;
    #pragma unroll
    for (int i = 0; i < 8; ++i) {
        int idx = threadIdx.x + i * 128;
        int row = idx >> 3, seg = idx & 7;
        uint32_t so = row * STRIDE + seg * 16;
        cp16(abase + so,
             Asrc + ((size_t)(m0 + row) * KA + chunk * BKE) * 2 + seg * 16);
        cp16(bbase + so,
             Bsrc + ((size_t)(n0 + row) * KB + bchunk * BKE) * 2 + seg * 16);
    }
    CP_COMMIT();
}

__global__ void __launch_bounds__(128, 1)
k_gemm_mma(float* __restrict__ pred) {
    extern __shared__ char smem[];
    uint32_t sb = smem_u32(smem);
    const int tid  = threadIdx.x;
    const int wid  = tid >> 5;
    const int lane = tid & 31;
    const int wm   = wid >> 1;          // 0..1
    const int wn   = wid & 1;           // 0..1
    const int g    = lane >> 2;         // 0..7
    const int tig  = lane & 3;          // 0..3
    const int m0   = blockIdx.x * 128;  // m fastest -> B-tile L2 reuse
    const int n0   = blockIdx.y * 128;

    // per-lane ldmatrix base offsets (within a tile)
    const uint32_t a_off = (uint32_t)(wm * 64 + (lane & 7) + ((lane >> 3) & 1) * 8) * STRIDE
                         + ((lane >> 4) & 1) * 16;
    const uint32_t b_off = (uint32_t)(wn * 64 + (lane & 7) + ((lane >> 4) & 1) * 8) * STRIDE
                         + ((lane >> 3) & 1) * 16;

    float acc[4][8][4];
    #pragma unroll
    for (int i = 0; i < 4; ++i)
        #pragma unroll
        for (int j = 0; j < 8; ++j)
            #pragma unroll
            for (int r = 0; r < 4; ++r) acc[i][j][r] = 0.0f;

    load_tiles(0, 0, sb, m0, n0);
    load_tiles(1, 1, sb, m0, n0);

    for (int j = 0; j < NCH; ++j) {
        if (j + 1 < NCH) { CP_WAIT1(); } else { CP_WAIT0(); }
        __syncthreads();
        const int stage = j & 1;
        const uint32_t at = sb + stage * STAGE_B + a_off;
        const uint32_t bt = sb + stage * STAGE_B + TILE_B + b_off;

        #pragma unroll
        for (int kk = 0; kk < 4; ++kk) {
            uint32_t a[4][4], b[8][2];
            #pragma unroll
            for (int mi = 0; mi < 4; ++mi)
                ldsm4(a[mi], at + mi * 16 * STRIDE + kk * 32);
            #pragma unroll
            for (int p = 0; p < 4; ++p) {
                uint32_t r[4];
                ldsm4(r, bt + p * 16 * STRIDE + kk * 32);
                b[2 * p][0]     = r[0];
                b[2 * p][1]     = r[1];
                b[2 * p + 1][0] = r[2];
                b[2 * p + 1][1] = r[3];
            }
            #pragma unroll
            for (int mi = 0; mi < 4; ++mi)
                #pragma unroll
                for (int nj = 0; nj < 8; ++nj)
                    mma16816(acc[mi][nj], a[mi], b[nj]);
        }
        __syncthreads();                        // stage free before refill
        if (j + 2 < NCH) load_tiles(j + 2, stage, sb, m0, n0);
    }

    // ---- fused ArcFace epilogue ----
    const float tn = g_tnew;
    #pragma unroll
    for (int mi = 0; mi < 4; ++mi) {
        int r0 = m0 + wm * 64 + mi * 16 + g;
        #pragma unroll
        for (int half = 0; half < 2; ++half) {
            int brow = r0 + half * 8;
            int tgt   = g_targets[brow];
            float ctm = g_ctm[brow];
            float ftl = g_ftl[brow];
            size_t rowbase = (size_t)brow * C;
            #pragma unroll
            for (int nj = 0; nj < 8; ++nj) {
                int c = n0 + wn * 64 + nj * 8 + tig * 2;
                float v0 = acc[mi][nj][half * 2 + 0];
                float v1 = acc[mi][nj][half * 2 + 1];
                v0 = (v0 > ctm) ? v0 * (tn + v0) : v0;
                v1 = (v1 > ctm) ? v1 * (tn + v1) : v1;
                if (c == tgt)     v0 = ftl;
                if (c + 1 == tgt) v1 = ftl;
                v0 *= S_SCALE;
                v1 *= S_SCALE;
                if (c + 1 < C) {
                    *(float2*)&pred[rowbase + c] = make_float2(v0, v1);
                } else if (c < C) {
                    pred[rowbase + c] = v0;
                }
            }
        }
    }
}

// ---------------- launch ----------------
extern "C" void kernel_launch(void* const* d_in, const int* in_sizes, int n_in,
                              void* d_out, int out_size) {
    const float* features = (const float*)d_in[0];
    const int*   traw     = (const int*)d_in[1];
    const float* weight   = (const float*)d_in[2];
    const float* t_in     = (const float*)d_in[3];

    float* out    = (float*)d_out;
    float* pred   = out;                        // [B, C]
    float* newW   = out + PRED_ELEMS;           // [C, D]
    float* out_t  = out + PRED_ELEMS + W_ELEMS; // [1]
    float* scratch = pred;                      // reuse pred region as segment-sum scratch

    cudaFuncSetAttribute(k_gemm_mma, cudaFuncAttributeMaxDynamicSharedMemorySize, SMEM_G);

    k_unpack_targets<<<1, B>>>(traw);
    k_normalize_tl<<<B, D>>>(features, weight);
    k_row_params<<<1, B>>>(t_in, out_t);
    k_zero_counts<<<(C + 255) / 256, 256>>>();
    k_zero_scratch<<<B, D>>>(scratch);
    k_accumulate<<<B, D>>>(scratch);
    k_weight_update<<<CPAD / 8, 256>>>(weight, scratch, newW);

    dim3 grid(B / 128, CPAD / 128);             // (4, 782), m fastest
    k_gemm_mma<<<grid, 128, SMEM_G>>>(pred);
}